// round 10
// baseline (speedup 1.0000x reference)
#include <cuda_runtime.h>
#include <cuda_fp16.h>
#include <cstdint>

// ---------------- problem constants ----------------
#define NTOK   16384
#define DDIM   512
#define HDIM   1408
#define NEXP   8
#define KTOP   2
#define NPAIR  (NTOK*KTOP)
#define MTILE  128
#define MAX_MT 264
#define NSM    148
#define PGRID  (2 * NSM)      // persistent grid: 2 CTAs/SM

// ---------------- device scratch ----------------
__device__ __half g_xh [(size_t)NTOK * DDIM];
__device__ __half g_w1h[(size_t)NEXP * HDIM * DDIM];
__device__ __half g_w3h[(size_t)NEXP * HDIM * DDIM];
__device__ __half g_w2h[(size_t)NEXP * DDIM * HDIM];
__device__ __half g_h  [(size_t)NPAIR * HDIM];
__device__ float  g_y  [(size_t)NPAIR * DDIM];
__device__ int    g_tok_of_pair[NPAIR];
__device__ int    g_slot[NTOK * KTOP];
__device__ int    g_exp_of_tok[NTOK * KTOP];
__device__ float  g_wt_of_tok[NTOK * KTOP];
__device__ int    g_counts[NEXP];
__device__ int    g_cursor[NEXP];
__device__ int    g_offsets[NEXP + 1];
__device__ float  g_usage[NEXP];
__device__ int    g_tile_expert[MAX_MT];
__device__ int    g_tile_row[MAX_MT];
__device__ int    g_ntiles;

// ---------------- helpers ----------------
__device__ __forceinline__ uint32_t smem_u32(const void* p) {
    uint32_t a;
    asm("{ .reg .u64 t; cvta.to.shared.u64 t, %1; cvt.u32.u64 %0, t; }" : "=r"(a) : "l"(p));
    return a;
}
__device__ __forceinline__ void cp16(uint32_t dst, const void* src) {
    asm volatile("cp.async.cg.shared.global [%0], [%1], 16;" :: "r"(dst), "l"(src));
}
#define CP_COMMIT() asm volatile("cp.async.commit_group;" ::: "memory")
#define CP_WAIT1()  asm volatile("cp.async.wait_group 1;" ::: "memory")
#define SWZ(x) ((x) ^ (((x) >> 3) & 0x70))

#define LDSM4(r0, r1, r2, r3, addr) \
    asm volatile("ldmatrix.sync.aligned.m8n8.x4.shared.b16 {%0,%1,%2,%3}, [%4];" \
        : "=r"(r0), "=r"(r1), "=r"(r2), "=r"(r3) : "r"(addr))

__device__ __forceinline__ void mma_f16(float* c, const uint32_t* a, const uint32_t* b) {
    asm volatile(
        "mma.sync.aligned.m16n8k16.row.col.f32.f16.f16.f32 "
        "{%0,%1,%2,%3}, {%4,%5,%6,%7}, {%8,%9}, {%0,%1,%2,%3};\n"
        : "+f"(c[0]), "+f"(c[1]), "+f"(c[2]), "+f"(c[3])
        : "r"(a[0]), "r"(a[1]), "r"(a[2]), "r"(a[3]), "r"(b[0]), "r"(b[1]));
}

// ---------------- small kernels (verified) ----------------
__global__ void init_kernel() {
    int i = threadIdx.x;
    if (i < NEXP) { g_counts[i] = 0; g_cursor[i] = 0; g_usage[i] = 0.f; }
}

__global__ void __launch_bounds__(256) router_kernel(const float* __restrict__ x,
                                                     const float* __restrict__ rw) {
    int warp = threadIdx.x >> 5, lane = threadIdx.x & 31;
    int tok = blockIdx.x * 8 + warp;
    if (tok >= NTOK) return;
    const float* xr = x + (size_t)tok * DDIM;
    float xv[16];
#pragma unroll
    for (int i = 0; i < 16; i++) xv[i] = xr[lane + 32 * i];
    float logits[NEXP];
#pragma unroll
    for (int e = 0; e < NEXP; e++) {
        const float* wr = rw + e * DDIM;
        float s = 0.f;
#pragma unroll
        for (int i = 0; i < 16; i++) s += xv[i] * wr[lane + 32 * i];
#pragma unroll
        for (int o = 16; o > 0; o >>= 1) s += __shfl_xor_sync(0xffffffffu, s, o);
        logits[e] = s;
    }
    if (lane == 0) {
        float m = logits[0];
#pragma unroll
        for (int e = 1; e < NEXP; e++) m = fmaxf(m, logits[e]);
        float p[NEXP], Z = 0.f;
#pragma unroll
        for (int e = 0; e < NEXP; e++) { p[e] = __expf(logits[e] - m); Z += p[e]; }
        float inv = 1.f / Z;
        int a = 0;
#pragma unroll
        for (int e = 1; e < NEXP; e++) if (p[e] > p[a]) a = e;
        int b = (a == 0) ? 1 : 0;
#pragma unroll
        for (int e = 0; e < NEXP; e++) { if (e == a) continue; if (p[e] > p[b]) b = e; }
        float pa = p[a] * inv, pb = p[b] * inv, ws = pa + pb;
        g_exp_of_tok[tok * 2 + 0] = a;
        g_exp_of_tok[tok * 2 + 1] = b;
        g_wt_of_tok[tok * 2 + 0] = pa / ws;
        g_wt_of_tok[tok * 2 + 1] = pb / ws;
        atomicAdd(&g_counts[a], 1);
        atomicAdd(&g_counts[b], 1);
#pragma unroll
        for (int e = 0; e < NEXP; e++) atomicAdd(&g_usage[e], p[e] * inv);
    }
}

__global__ void scan_kernel() {
    if (threadIdx.x != 0) return;
    int off = 0;
    for (int e = 0; e < NEXP; e++) { g_offsets[e] = off; off += g_counts[e]; }
    g_offsets[NEXP] = off;
    int nt = 0;
    for (int e = 0; e < NEXP; e++) {
        int cnt = g_counts[e];
        for (int r = 0; r < cnt; r += MTILE) {
            g_tile_expert[nt] = e;
            g_tile_row[nt] = g_offsets[e] + r;
            nt++;
        }
    }
    g_ntiles = nt;
}

__global__ void build_kernel() {
    int i = blockIdx.x * blockDim.x + threadIdx.x;
    if (i >= NTOK * KTOP) return;
    int e = g_exp_of_tok[i];
    int pos = g_offsets[e] + atomicAdd(&g_cursor[e], 1);
    g_tok_of_pair[pos] = i >> 1;
    g_slot[i] = pos;
}

__global__ void cvt_kernel(const float4* __restrict__ src, uint4* __restrict__ dst, int n8) {
    int i = blockIdx.x * blockDim.x + threadIdx.x;
    if (i >= n8) return;
    float4 s0 = src[2 * i], s1 = src[2 * i + 1];
    __half2 h0 = __floats2half2_rn(s0.x, s0.y);
    __half2 h1 = __floats2half2_rn(s0.z, s0.w);
    __half2 h2 = __floats2half2_rn(s1.x, s1.y);
    __half2 h3 = __floats2half2_rn(s1.z, s1.w);
    uint4 o;
    o.x = *(uint32_t*)&h0; o.y = *(uint32_t*)&h1;
    o.z = *(uint32_t*)&h2; o.w = *(uint32_t*)&h3;
    dst[i] = o;
}

// ============================================================
// Persistent GEMMs: CTA 128M, BK=64 fp16, 3-stage cp.async ring
// that carries across work-item boundaries. 2 CTAs/SM.
// ============================================================
#define BK        64
#define STG_BYTES 32768
#define BOFF      16384
#define GSMEM     (3 * STG_BYTES)

// ---------------- GEMM1: h = silu(x@w1^T)*(x@w3^T) ----------------
#define G1_NB (HDIM / 64)   // 22 N-blocks
#define G1_NC (DDIM / BK)   // 8 chunks per tile

__global__ void __launch_bounds__(256, 2) gemm1_mm() {
    extern __shared__ char smem[];
    uint32_t sb = smem_u32(smem);
    int tid = threadIdx.x;
    int G = gridDim.x, bid = blockIdx.x;
    int nwi = g_ntiles * G1_NB;
    if (bid >= nwi) return;
    int nmy = (nwi - 1 - bid) / G + 1;
    int total = nmy * G1_NC;

    int lr = tid >> 1, half = tid & 1;
    uint32_t abase = lr * 128 + half * 64;
    int lrb = lr & 63;

    const __half* asrc; const __half* bsrc;
    int lwi = bid;
    {
        int mt = lwi / G1_NB, nb = lwi - mt * G1_NB;
        int e = g_tile_expert[mt], row0 = g_tile_row[mt];
        int aidx = row0 + lr; if (aidx >= NPAIR) aidx = NPAIR - 1;
        asrc = g_xh + (size_t)g_tok_of_pair[aidx] * DDIM + half * 32;
        const __half* wbase = (lr < 64) ? g_w1h : g_w3h;
        bsrc = wbase + (size_t)e * HDIM * DDIM + (size_t)(nb * 64 + lrb) * DDIM + half * 32;
    }

#define G1_ISSUE(kc, st) do { \
    uint32_t _s = sb + (st) * STG_BYTES; \
    const __half* _a = asrc + (kc) * BK; \
    const __half* _b = bsrc + (kc) * BK; \
    _Pragma("unroll") for (int c = 0; c < 4; c++) { \
        cp16(_s + SWZ(abase + c * 16), _a + c * 8); \
        cp16(_s + BOFF + SWZ(abase + c * 16), _b + c * 8); \
    } \
    CP_COMMIT(); \
} while (0)

    G1_ISSUE(0, 0);
    G1_ISSUE(1, 1);
    int lq = 2;

    int w = tid >> 5, lane = tid & 31;
    int wm = (w & 3) * 32, wn = (w >> 2) * 32;
    int l7 = lane & 7;
    int rA = l7 + ((lane >> 3) & 1) * 8;
    int cA = ((lane >> 4) & 1) * 16;
    int rB = l7 + ((lane >> 4) & 1) * 8;
    int cB = ((lane >> 3) & 1) * 16;
    int gid = lane >> 2, tig = lane & 3;

    float acc1[2][4][4] = {}, acc3[2][4][4] = {};
    int cwi = bid;

    for (int c = 0; c < total; c++) {
        int kc = c & (G1_NC - 1);
        int st = c % 3;
        CP_WAIT1();
        __syncthreads();
        if (lq < total) {
            int lkc = lq & (G1_NC - 1);
            if (lkc == 0) {
                lwi += G;
                int mt = lwi / G1_NB, nb = lwi - mt * G1_NB;
                int e = g_tile_expert[mt], row0 = g_tile_row[mt];
                int aidx = row0 + lr; if (aidx >= NPAIR) aidx = NPAIR - 1;
                asrc = g_xh + (size_t)g_tok_of_pair[aidx] * DDIM + half * 32;
                const __half* wbase = (lr < 64) ? g_w1h : g_w3h;
                bsrc = wbase + (size_t)e * HDIM * DDIM + (size_t)(nb * 64 + lrb) * DDIM + half * 32;
            }
            G1_ISSUE(lkc, lq % 3);
        } else CP_COMMIT();
        lq++;

        uint32_t sA = sb + st * STG_BYTES;
        uint32_t sB = sA + BOFF;
#pragma unroll
        for (int kk = 0; kk < 4; kk++) {
            uint32_t a[2][4];
#pragma unroll
            for (int m = 0; m < 2; m++)
                LDSM4(a[m][0], a[m][1], a[m][2], a[m][3],
                      sA + SWZ((wm + m * 16 + rA) * 128 + kk * 32 + cA));
            uint32_t b1[2][4], b3[2][4];
#pragma unroll
            for (int np = 0; np < 2; np++) {
                LDSM4(b1[np][0], b1[np][1], b1[np][2], b1[np][3],
                      sB + SWZ((wn + np * 16 + rB) * 128 + kk * 32 + cB));
                LDSM4(b3[np][0], b3[np][1], b3[np][2], b3[np][3],
                      sB + SWZ((64 + wn + np * 16 + rB) * 128 + kk * 32 + cB));
            }
#pragma unroll
            for (int m = 0; m < 2; m++)
#pragma unroll
                for (int np = 0; np < 2; np++)
#pragma unroll
                    for (int j = 0; j < 2; j++) {
                        mma_f16(acc1[m][np * 2 + j], a[m], &b1[np][j * 2]);
                        mma_f16(acc3[m][np * 2 + j], a[m], &b3[np][j * 2]);
                    }
        }

        if (kc == G1_NC - 1) {
            // epilogue for cwi (overlaps in-flight loads of next tile)
            int mt = cwi / G1_NB, nb = cwi - mt * G1_NB;
            int e = g_tile_expert[mt], row0 = g_tile_row[mt];
            int valid = g_offsets[e + 1] - row0; if (valid > MTILE) valid = MTILE;
            int n0 = nb * 64;
#pragma unroll
            for (int m = 0; m < 2; m++)
#pragma unroll
                for (int no = 0; no < 4; no++) {
                    int col = n0 + wn + no * 8 + 2 * tig;
#pragma unroll
                    for (int hf = 0; hf < 2; hf++) {
                        int r = wm + m * 16 + gid + hf * 8;
                        if (r < valid) {
                            float z0 = acc1[m][no][hf * 2 + 0];
                            float z1 = acc1[m][no][hf * 2 + 1];
                            float s0 = z0 / (1.f + __expf(-z0));
                            float s1 = z1 / (1.f + __expf(-z1));
                            __half2 v = __floats2half2_rn(s0 * acc3[m][no][hf * 2 + 0],
                                                          s1 * acc3[m][no][hf * 2 + 1]);
                            *(__half2*)(g_h + (size_t)(row0 + r) * HDIM + col) = v;
                        }
                    }
                }
            cwi += G;
#pragma unroll
            for (int m = 0; m < 2; m++)
#pragma unroll
                for (int no = 0; no < 4; no++)
#pragma unroll
                    for (int j = 0; j < 4; j++) { acc1[m][no][j] = 0.f; acc3[m][no][j] = 0.f; }
        }
    }
}

// ---------------- GEMM2: y = h @ w2^T ----------------
#define G2_NB (DDIM / 128)  // 4 N-blocks
#define G2_NC (HDIM / BK)   // 22 chunks per tile

__global__ void __launch_bounds__(256, 2) gemm2_mm() {
    extern __shared__ char smem[];
    uint32_t sb = smem_u32(smem);
    int tid = threadIdx.x;
    int G = gridDim.x, bid = blockIdx.x;
    int nwi = g_ntiles * G2_NB;
    if (bid >= nwi) return;
    int nmy = (nwi - 1 - bid) / G + 1;
    int total = nmy * G2_NC;

    int lr = tid >> 1, half = tid & 1;
    uint32_t abase = lr * 128 + half * 64;

    const __half* asrc; const __half* bsrc;
    int lwi = bid;
    {
        int mt = lwi / G2_NB, nb = lwi - mt * G2_NB;
        int e = g_tile_expert[mt], row0 = g_tile_row[mt];
        int aidx = row0 + lr; if (aidx >= NPAIR) aidx = NPAIR - 1;
        asrc = g_h + (size_t)aidx * HDIM + half * 32;
        bsrc = g_w2h + (size_t)e * DDIM * HDIM + (size_t)(nb * 128 + lr) * HDIM + half * 32;
    }

#define G2_ISSUE(kc, st) do { \
    uint32_t _s = sb + (st) * STG_BYTES; \
    const __half* _a = asrc + (kc) * BK; \
    const __half* _b = bsrc + (kc) * BK; \
    _Pragma("unroll") for (int c = 0; c < 4; c++) { \
        cp16(_s + SWZ(abase + c * 16), _a + c * 8); \
        cp16(_s + BOFF + SWZ(abase + c * 16), _b + c * 8); \
    } \
    CP_COMMIT(); \
} while (0)

    G2_ISSUE(0, 0);
    G2_ISSUE(1, 1);
    int lq = 2;

    int w = tid >> 5, lane = tid & 31;
    int wm = (w & 3) * 32, wn = (w >> 2) * 64;
    int l7 = lane & 7;
    int rA = l7 + ((lane >> 3) & 1) * 8;
    int cA = ((lane >> 4) & 1) * 16;
    int rB = l7 + ((lane >> 4) & 1) * 8;
    int cB = ((lane >> 3) & 1) * 16;
    int gid = lane >> 2, tig = lane & 3;

    float acc[2][8][4] = {};
    int cwi = bid;
    int ckc = 0;

    for (int c = 0; c < total; c++) {
        int st = c % 3;
        CP_WAIT1();
        __syncthreads();
        if (lq < total) {
            int lkc = lq % G2_NC;
            if (lkc == 0) {
                lwi += G;
                int mt = lwi / G2_NB, nb = lwi - mt * G2_NB;
                int e = g_tile_expert[mt], row0 = g_tile_row[mt];
                int aidx = row0 + lr; if (aidx >= NPAIR) aidx = NPAIR - 1;
                asrc = g_h + (size_t)aidx * HDIM + half * 32;
                bsrc = g_w2h + (size_t)e * DDIM * HDIM + (size_t)(nb * 128 + lr) * HDIM + half * 32;
            }
            G2_ISSUE(lkc, lq % 3);
        } else CP_COMMIT();
        lq++;

        uint32_t sA = sb + st * STG_BYTES;
        uint32_t sB = sA + BOFF;
#pragma unroll
        for (int kk = 0; kk < 4; kk++) {
            uint32_t a[2][4];
#pragma unroll
            for (int m = 0; m < 2; m++)
                LDSM4(a[m][0], a[m][1], a[m][2], a[m][3],
                      sA + SWZ((wm + m * 16 + rA) * 128 + kk * 32 + cA));
            uint32_t b[4][4];
#pragma unroll
            for (int np = 0; np < 4; np++)
                LDSM4(b[np][0], b[np][1], b[np][2], b[np][3],
                      sB + SWZ((wn + np * 16 + rB) * 128 + kk * 32 + cB));
#pragma unroll
            for (int m = 0; m < 2; m++)
#pragma unroll
                for (int np = 0; np < 4; np++)
#pragma unroll
                    for (int j = 0; j < 2; j++)
                        mma_f16(acc[m][np * 2 + j], a[m], &b[np][j * 2]);
        }

        if (++ckc == G2_NC) {
            ckc = 0;
            int mt = cwi / G2_NB, nb = cwi - mt * G2_NB;
            int row0 = g_tile_row[mt];
            int e = g_tile_expert[mt];
            int valid = g_offsets[e + 1] - row0; if (valid > MTILE) valid = MTILE;
            int n0 = nb * 128;
#pragma unroll
            for (int m = 0; m < 2; m++)
#pragma unroll
                for (int no = 0; no < 8; no++) {
                    int col = n0 + wn + no * 8 + 2 * tig;
#pragma unroll
                    for (int hf = 0; hf < 2; hf++) {
                        int r = wm + m * 16 + gid + hf * 8;
                        if (r < valid) {
                            float2 v;
                            v.x = acc[m][no][hf * 2 + 0];
                            v.y = acc[m][no][hf * 2 + 1];
                            *(float2*)(g_y + (size_t)(row0 + r) * DDIM + col) = v;
                        }
                    }
                }
            cwi += G;
#pragma unroll
            for (int m = 0; m < 2; m++)
#pragma unroll
                for (int no = 0; no < 8; no++)
#pragma unroll
                    for (int j = 0; j < 4; j++) acc[m][no][j] = 0.f;
        }
    }
}

// ---------------- combine + aux ----------------
__global__ void combine_kernel(float* __restrict__ out) {
    int i = blockIdx.x * blockDim.x + threadIdx.x;
    const int D4 = DDIM / 4;
    if (i >= NTOK * D4) return;
    int tok = i / D4;
    int d4 = i - tok * D4;
    int s0 = g_slot[tok * 2 + 0], s1 = g_slot[tok * 2 + 1];
    float w0 = g_wt_of_tok[tok * 2 + 0], w1 = g_wt_of_tok[tok * 2 + 1];
    const float4* y4 = (const float4*)g_y;
    float4 a = y4[(size_t)s0 * D4 + d4];
    float4 b = y4[(size_t)s1 * D4 + d4];
    float4 r;
    r.x = w0 * a.x + w1 * b.x;
    r.y = w0 * a.y + w1 * b.y;
    r.z = w0 * a.z + w1 * b.z;
    r.w = w0 * a.w + w1 * b.w;
    ((float4*)out)[i] = r;
}

__global__ void finalize_kernel(float* __restrict__ out, int out_size) {
    if (threadIdx.x != 0 || blockIdx.x != 0) return;
    if (out_size > NTOK * DDIM) {
        float s = 0.f;
        for (int e = 0; e < NEXP; e++) {
            float u = g_usage[e] / (float)NTOK;
            s += u * u;
        }
        out[NTOK * DDIM] = (float)NEXP * 0.01f * s;
    }
}

// ---------------- launch ----------------
extern "C" void kernel_launch(void* const* d_in, const int* in_sizes, int n_in,
                              void* d_out, int out_size) {
    const float* x  = (const float*)d_in[0];
    const float* rw = (const float*)d_in[1];
    const float* w1 = (const float*)d_in[2];
    const float* w2 = (const float*)d_in[3];
    const float* w3 = (const float*)d_in[4];
    float* out = (float*)d_out;

    cudaFuncSetAttribute(gemm1_mm, cudaFuncAttributeMaxDynamicSharedMemorySize, GSMEM);
    cudaFuncSetAttribute(gemm2_mm, cudaFuncAttributeMaxDynamicSharedMemorySize, GSMEM);

    __half* gxh;  cudaGetSymbolAddress((void**)&gxh,  g_xh);
    __half* gw1;  cudaGetSymbolAddress((void**)&gw1,  g_w1h);
    __half* gw3;  cudaGetSymbolAddress((void**)&gw3,  g_w3h);
    __half* gw2;  cudaGetSymbolAddress((void**)&gw2,  g_w2h);

    init_kernel<<<1, 32>>>();
    router_kernel<<<NTOK / 8, 256>>>(x, rw);
    scan_kernel<<<1, 32>>>();
    build_kernel<<<(NTOK * KTOP + 255) / 256, 256>>>();

    int nx8 = NTOK * DDIM / 8, nw8 = NEXP * HDIM * DDIM / 8;
    cvt_kernel<<<(nx8 + 255) / 256, 256>>>((const float4*)x,  (uint4*)gxh, nx8);
    cvt_kernel<<<(nw8 + 255) / 256, 256>>>((const float4*)w1, (uint4*)gw1, nw8);
    cvt_kernel<<<(nw8 + 255) / 256, 256>>>((const float4*)w3, (uint4*)gw3, nw8);
    cvt_kernel<<<(nw8 + 255) / 256, 256>>>((const float4*)w2, (uint4*)gw2, nw8);

    gemm1_mm<<<PGRID, 256, GSMEM>>>();
    gemm2_mm<<<PGRID, 256, GSMEM>>>();
    combine_kernel<<<(NTOK * (DDIM / 4) + 255) / 256, 256>>>(out);
    finalize_kernel<<<1, 32>>>(out, out_size);
}